// round 14
// baseline (speedup 1.0000x reference)
#include <cuda_runtime.h>
#include <cuda_bf16.h>

// Problem constants (fixed by setup_inputs): B=2, L=16, C=16, H=64, W=64
#define PB 2
#define PL 16
#define PC 16
#define PH 64
#define PW 64
#define PHW (PH * PW)          // 4096

#define FLOWS_ELEMS  (PB * PL * 2 * PHW)     // 262144
#define IMAGES_ELEMS (PB * PL * PC * PHW)    // 2097152

// Scratch (allocation-free: __device__ globals)
// cum2[b][l][pix] = (cum_x, cum_y) : B*L*HW float2 = 1 MB
__device__ float2 g_cum2[PB * PL * PHW];
// imgT[b][l][h][w][c] as float4 (c packed, 16B aligned): B*L*HW*4 float4 = 8 MB
__device__ float4 g_imgT[PB * PL * PHW * (PC / 4)];

#define CUM_BLOCKS   ((PB * PHW) / 256)              // 32
#define TRANS_BLOCKS ((PB * PL * PHW) / 256)         // 512

#define PIX_PER_BLK 128                              // pixels per pscan block

// ---------------------------------------------------------------------------
// Fused prep kernel (single launch):
//  blocks [0, CUM_BLOCKS)              : cumsum of flows over L per (b,h,w)
//  blocks [CUM_BLOCKS, +TRANS_BLOCKS)  : transpose images -> [B][L][H][W][C]
// ---------------------------------------------------------------------------
__global__ void prep_kernel(const float* __restrict__ flows,
                            const float* __restrict__ images)
{
    if (blockIdx.x < CUM_BLOCKS) {
        int s = blockIdx.x * blockDim.x + threadIdx.x;   // 0 .. B*HW-1
        int b   = s / PHW;
        int pix = s - b * PHW;
        const float* src = flows + (size_t)b * (PL * 2 * PHW) + pix;
        float2* dst = g_cum2 + (size_t)b * (PL * PHW) + pix;
        float cx = 0.0f, cy = 0.0f;
#pragma unroll
        for (int l = 0; l < PL; ++l) {
            cx += src[(l * 2 + 0) * PHW];
            cy += src[(l * 2 + 1) * PHW];
            dst[l * PHW] = make_float2(cx, cy);
        }
    } else {
        int t = (blockIdx.x - CUM_BLOCKS) * blockDim.x + threadIdx.x; // 0 .. B*L*HW-1
        int bl  = t / PHW;
        int pix = t - bl * PHW;
        const float* src = images + (size_t)bl * (PC * PHW) + pix;
        float v[PC];
#pragma unroll
        for (int c = 0; c < PC; ++c) v[c] = src[c * PHW];
        float4* dst = g_imgT + (size_t)t * (PC / 4);
#pragma unroll
        for (int k = 0; k < PC / 4; ++k)
            dst[k] = make_float4(v[4 * k], v[4 * k + 1], v[4 * k + 2], v[4 * k + 3]);
    }
}

// ---------------------------------------------------------------------------
// Main pairwise bilinear gather-scan.
// block = 256 threads = 128 pixels x 2 channel-halves; grid = (HW/128, L, B).
// Each lane handles 8 channels (2 float4s) -> per-pixel coordinate/weight
// math is duplicated only 2x (was 4x), cutting fma/alu issue slots ~28%,
// and each lane issues 8 corner LDG.128s per j (2x the per-warp MLP).
// __launch_bounds__(256,3) gives an 85-reg budget so the 8-in-flight
// live set (~40 data regs) does not spill; 24 warps/SM x 8 LDGs in flight
// exceeds the old 30 x 4.
// The 2 lanes of a pixel still cover a contiguous 64B channel block per
// corner. cum staged in smem; LPT heavy-i-first dispatch; reference-exact
// fp ordering (rel first, then base + rel).
// ---------------------------------------------------------------------------
__device__ __forceinline__ float wrapg(float g)
{
    // jnp.mod(g + 1, 2) - 1  (floor-mod; power-of-two divisor -> exact)
    float t = g + 1.0f;
    t = t - 2.0f * floorf(t * 0.5f);
    float r = t - 1.0f;
    return (r < -1.0f) ? r + 2.0f : r;   // matches the reference fixup
}

__global__ void __launch_bounds__(256, 3)
pscan_kernel(float* __restrict__ out)
{
    __shared__ float2 s_cum[PL * PIX_PER_BLK];       // up to 16 KB

    int tid = threadIdx.x;
    int cg  = tid & 1;                               // channel half: 8 floats
    int lp  = tid >> 1;                              // local pixel 0..127
    int pix = blockIdx.x * PIX_PER_BLK + lp;         // 0..4095
    int i   = (PL - 1) - blockIdx.y;                 // heavy CTAs first
    int b   = blockIdx.z;
    int h   = pix >> 6;
    int w   = pix & 63;

    // Stage cum[j][pix] for j = 0..i and all 128 block pixels into smem.
    const float2* cumBase = g_cum2 + (size_t)b * (PL * PHW) + blockIdx.x * PIX_PER_BLK;
    for (int idx = tid; idx < (i + 1) * PIX_PER_BLK; idx += 256) {
        int jj = idx >> 7;
        int pp = idx & (PIX_PER_BLK - 1);
        s_cum[idx] = cumBase[jj * PHW + pp];
    }
    __syncthreads();

    float bx = (w + 0.5f) * (2.0f / PW) - 1.0f;
    float by = (h + 0.5f) * (2.0f / PH) - 1.0f;

    float2 ci = s_cum[i * PIX_PER_BLK + lp];
    float cix = ci.x;
    float ciy = ci.y;

    // This lane's 2 float4s start at channel-block index cg*2.
    const float4* imgB = g_imgT + (size_t)(b * PL) * PHW * (PC / 4) + cg * 2;

    float4 acc0 = make_float4(0.f, 0.f, 0.f, 0.f);
    float4 acc1 = make_float4(0.f, 0.f, 0.f, 0.f);

#pragma unroll 2
    for (int j = 0; j <= i; ++j) {
        float2 cj = s_cum[j * PIX_PER_BLK + lp];

        // Reference order: rel first, then base + rel.
        float relx = cix - cj.x;
        float rely = ciy - cj.y;
        float gx = wrapg(bx + relx);
        float gy = wrapg(by + rely);
        float rx = (gx + 1.0f) * (0.5f * PW) - 0.5f;
        float ry = (gy + 1.0f) * (0.5f * PH) - 0.5f;

        float x0f = floorf(rx);
        float y0f = floorf(ry);
        int   x0  = (int)x0f;
        int   y0  = (int)y0f;
        float fx  = rx - x0f;
        float fy  = ry - y0f;

        // gx,gy in [-1,1) => x0 in [-1,63], x1 in [0,64]; one-sided masks suffice
        float mx0 = (x0 >= 0)      ? 1.0f : 0.0f;
        float mx1 = (x0 <  PW - 1) ? 1.0f : 0.0f;
        float my0 = (y0 >= 0)      ? 1.0f : 0.0f;
        float my1 = (y0 <  PH - 1) ? 1.0f : 0.0f;

        int cx0 = max(x0, 0);
        int cx1 = min(x0 + 1, PW - 1);
        int cy0 = max(y0, 0);
        int cy1 = min(y0 + 1, PH - 1);

        const float4* base = imgB + (size_t)j * PHW * (PC / 4);
        int offA = (cy0 * PW + cx0) * (PC / 4);
        int offB = (cy1 * PW + cx0) * (PC / 4);
        int offC = (cy0 * PW + cx1) * (PC / 4);
        int offD = (cy1 * PW + cx1) * (PC / 4);

        // 8 independent gathers in flight before any consumer.
        float4 va0 = base[offA];  float4 va1 = base[offA + 1];
        float4 vb0 = base[offB];  float4 vb1 = base[offB + 1];
        float4 vc0 = base[offC];  float4 vc1 = base[offC + 1];
        float4 vd0 = base[offD];  float4 vd1 = base[offD + 1];

        float wa = (1.0f - fx) * (1.0f - fy) * (mx0 * my0);  // (x0,y0)
        float wb = (1.0f - fx) * fy          * (mx0 * my1);  // (x0,y1)
        float wc = fx * (1.0f - fy)          * (mx1 * my0);  // (x1,y0)
        float wd = fx * fy                   * (mx1 * my1);  // (x1,y1)

        acc0.x += wa * va0.x + wb * vb0.x + wc * vc0.x + wd * vd0.x;
        acc0.y += wa * va0.y + wb * vb0.y + wc * vc0.y + wd * vd0.y;
        acc0.z += wa * va0.z + wb * vb0.z + wc * vc0.z + wd * vd0.z;
        acc0.w += wa * va0.w + wb * vb0.w + wc * vc0.w + wd * vd0.w;
        acc1.x += wa * va1.x + wb * vb1.x + wc * vc1.x + wd * vd1.x;
        acc1.y += wa * va1.y + wb * vb1.y + wc * vc1.y + wd * vd1.y;
        acc1.z += wa * va1.z + wb * vb1.z + wc * vc1.z + wd * vd1.z;
        acc1.w += wa * va1.w + wb * vb1.w + wc * vc1.w + wd * vd1.w;
    }

    // out[b][i][c][h][w], c = cg*8 .. cg*8+7
    float* op = out + ((size_t)(b * PL + i) * PC + cg * 8) * PHW + pix;
    op[0 * PHW] = acc0.x;
    op[1 * PHW] = acc0.y;
    op[2 * PHW] = acc0.z;
    op[3 * PHW] = acc0.w;
    op[4 * PHW] = acc1.x;
    op[5 * PHW] = acc1.y;
    op[6 * PHW] = acc1.z;
    op[7 * PHW] = acc1.w;
}

// ---------------------------------------------------------------------------
extern "C" void kernel_launch(void* const* d_in, const int* in_sizes, int n_in,
                              void* d_out, int out_size)
{
    // Bind inputs by element count (robust to metadata ordering):
    // flows = 262144 elems, images = 2097152 elems.
    const float* flows  = (const float*)d_in[0];
    const float* images = (const float*)d_in[1];
    if (n_in >= 2 && in_sizes[0] == IMAGES_ELEMS && in_sizes[1] == FLOWS_ELEMS) {
        flows  = (const float*)d_in[1];
        images = (const float*)d_in[0];
    }
    float* out = (float*)d_out;                    // (2,16,16,64,64)

    // 1) fused prep: cumsum (32 blocks) + channel-last transpose (512 blocks)
    prep_kernel<<<CUM_BLOCKS + TRANS_BLOCKS, 256>>>(flows, images);

    // 2) main pairwise scan: 128 pixels x 2 channel-halves per block
    dim3 grid(PHW / PIX_PER_BLK, PL, PB);
    pscan_kernel<<<grid, 256>>>(out);
}